// round 1
// baseline (speedup 1.0000x reference)
#include <cuda_runtime.h>

// ---------------------------------------------------------------------------
// MultiHeadAttentionBlock — softmax result is DISCARDED in the reference, so
// attention is LINEAR:  (Q K^T / 8) V  ==  Q (K^T V / 8).
// Per head, M = K^T V / 8 is only 64x64, and attn @ Wo^T folds into a
// per-batch combined weight WcombT. Pipeline:
//   1) Q = q Wq^T + bq ; K = k Wk^T + bk ; V = v Wv^T + bv   (3 big SGEMMs)
//   2) M[b,h] = K_h^T V_h / 8                                  (tiny)
//   3) WcombT[b][c][d=h*64+i] = sum_j M[b,h][i,j] * Wo[c, h*64+j]
//   4) out_b = Q_b @ WcombT_b^T + bo                           (2 big SGEMMs)
// All fp32 (rel_err ~1e-6).
// ---------------------------------------------------------------------------

#define Bsz 2
#define Ssz 2048
#define Dsz 1024
#define Hsz 16
#define DKsz 64

// Scratch (no cudaMalloc allowed)
__device__ float g_Q[Bsz * Ssz * Dsz];
__device__ float g_K[Bsz * Ssz * Dsz];
__device__ float g_V[Bsz * Ssz * Dsz];
__device__ float g_M[Bsz * Hsz * DKsz * DKsz];
__device__ float g_WT[Bsz * Dsz * Dsz];

// ---------------------------------------------------------------------------
// SGEMM (NT + bias): C[M,N] = A[M,K] @ B[N,K]^T + bias[N]
// 128x128 block tile, BK=16, 8x8 per thread, 256 threads.
// ---------------------------------------------------------------------------
__global__ __launch_bounds__(256, 2)
void sgemm_nt_bias(const float* __restrict__ A, const float* __restrict__ B,
                   const float* __restrict__ bias, float* __restrict__ C,
                   int M, int N, int K)
{
    __shared__ float As[16][128];
    __shared__ float Bs[16][128];

    const int bn = blockIdx.x * 128;
    const int bm = blockIdx.y * 128;
    const int tid = threadIdx.x;
    const int tr = tid >> 4;        // 0..15 (row group)
    const int tc = tid & 15;        // 0..15 (col group)
    const int lr = tid >> 2;        // 0..63 (load row)
    const int lc = (tid & 3) << 2;  // 0,4,8,12 (load col, floats)

    float acc[8][8];
    #pragma unroll
    for (int i = 0; i < 8; i++)
        #pragma unroll
        for (int j = 0; j < 8; j++) acc[i][j] = 0.f;

    for (int k0 = 0; k0 < K; k0 += 16) {
        #pragma unroll
        for (int r = 0; r < 128; r += 64) {
            float4 av = *(const float4*)(A + (size_t)(bm + lr + r) * K + k0 + lc);
            As[lc + 0][lr + r] = av.x;
            As[lc + 1][lr + r] = av.y;
            As[lc + 2][lr + r] = av.z;
            As[lc + 3][lr + r] = av.w;
            float4 bv = *(const float4*)(B + (size_t)(bn + lr + r) * K + k0 + lc);
            Bs[lc + 0][lr + r] = bv.x;
            Bs[lc + 1][lr + r] = bv.y;
            Bs[lc + 2][lr + r] = bv.z;
            Bs[lc + 3][lr + r] = bv.w;
        }
        __syncthreads();
        #pragma unroll
        for (int kk = 0; kk < 16; kk++) {
            float a[8], b[8];
            *(float4*)&a[0] = *(const float4*)&As[kk][tr * 8];
            *(float4*)&a[4] = *(const float4*)&As[kk][tr * 8 + 4];
            *(float4*)&b[0] = *(const float4*)&Bs[kk][tc * 8];
            *(float4*)&b[4] = *(const float4*)&Bs[kk][tc * 8 + 4];
            #pragma unroll
            for (int i = 0; i < 8; i++)
                #pragma unroll
                for (int j = 0; j < 8; j++)
                    acc[i][j] += a[i] * b[j];
        }
        __syncthreads();
    }

    float bcol[8];
    #pragma unroll
    for (int j = 0; j < 8; j++) bcol[j] = bias[bn + tc * 8 + j];

    #pragma unroll
    for (int i = 0; i < 8; i++) {
        const int row = bm + tr * 8 + i;
        #pragma unroll
        for (int j4 = 0; j4 < 8; j4 += 4) {
            const int col = bn + tc * 8 + j4;
            float4 o;
            o.x = acc[i][j4 + 0] + bcol[j4 + 0];
            o.y = acc[i][j4 + 1] + bcol[j4 + 1];
            o.z = acc[i][j4 + 2] + bcol[j4 + 2];
            o.w = acc[i][j4 + 3] + bcol[j4 + 3];
            *(float4*)(C + (size_t)row * N + col) = o;
        }
    }
}

// ---------------------------------------------------------------------------
// M[b,h][i][j] = (1/8) * sum_s K[b,s,h*64+i] * V[b,s,h*64+j]
// One block per (b,h); 256 threads; 4x4 outputs each; S-tiles of 32.
// ---------------------------------------------------------------------------
__global__ __launch_bounds__(256)
void ktv_kernel(const float* __restrict__ Kp, const float* __restrict__ Vp,
                float* __restrict__ Mout)
{
    __shared__ float Ks[32][64];
    __shared__ float Vs[32][64];
    const int b = blockIdx.x >> 4;
    const int h = blockIdx.x & 15;
    const int tid = threadIdx.x;
    const int ti = (tid >> 4) * 4;
    const int tj = (tid & 15) * 4;
    const size_t base = (size_t)b * Ssz * Dsz + h * DKsz;

    float acc[4][4] = {};
    for (int s0 = 0; s0 < Ssz; s0 += 32) {
        #pragma unroll
        for (int it = 0; it < 2; it++) {
            const int idx = tid + it * 256;      // 0..511 float4 slots
            const int srow = idx >> 4;           // 0..31
            const int scol = (idx & 15) << 2;    // 0..60
            *(float4*)&Ks[srow][scol] =
                *(const float4*)(Kp + base + (size_t)(s0 + srow) * Dsz + scol);
            *(float4*)&Vs[srow][scol] =
                *(const float4*)(Vp + base + (size_t)(s0 + srow) * Dsz + scol);
        }
        __syncthreads();
        #pragma unroll
        for (int ss = 0; ss < 32; ss++) {
            float4 ka = *(const float4*)&Ks[ss][ti];
            float4 vb = *(const float4*)&Vs[ss][tj];
            const float a[4] = {ka.x, ka.y, ka.z, ka.w};
            const float w[4] = {vb.x, vb.y, vb.z, vb.w};
            #pragma unroll
            for (int i = 0; i < 4; i++)
                #pragma unroll
                for (int j = 0; j < 4; j++) acc[i][j] += a[i] * w[j];
        }
        __syncthreads();
    }
    float* outp = Mout + (size_t)blockIdx.x * (DKsz * DKsz);
    #pragma unroll
    for (int i = 0; i < 4; i++) {
        float4 o;
        o.x = acc[i][0] * 0.125f;
        o.y = acc[i][1] * 0.125f;
        o.z = acc[i][2] * 0.125f;
        o.w = acc[i][3] * 0.125f;
        *(float4*)(outp + (ti + i) * DKsz + tj) = o;
    }
}

// ---------------------------------------------------------------------------
// WcombT[b][c][h*64+i] = sum_j M[b,h][i][j] * Wo[c][h*64+j]
// Block = (c-tile of 32, h, b). 256 threads; each thread 8 outputs.
// ---------------------------------------------------------------------------
__global__ __launch_bounds__(256)
void wcomb_kernel(const float* __restrict__ Mh, const float* __restrict__ Wo,
                  float* __restrict__ WT)
{
    __shared__ float MshT[64 * 64];   // [j][i] (transposed for conflict-free reads)
    __shared__ float WoSh[32][64];
    const int c0 = blockIdx.x * 32;
    const int h  = blockIdx.y;
    const int b  = blockIdx.z;
    const int tid = threadIdx.x;

    const float* Mp = Mh + (size_t)(b * Hsz + h) * (DKsz * DKsz);
    #pragma unroll
    for (int t = tid; t < 4096; t += 256) {
        const int i = t >> 6, j = t & 63;
        MshT[j * 64 + i] = Mp[t];
    }
    #pragma unroll
    for (int t = tid; t < 2048; t += 256) {
        const int cc = t >> 6, j = t & 63;
        WoSh[cc][j] = Wo[(size_t)(c0 + cc) * Dsz + h * DKsz + j];
    }
    __syncthreads();

    const int cc = tid >> 3;          // 0..31
    const int i0 = (tid & 7) * 8;     // 0..56
    float acc[8] = {};
    #pragma unroll
    for (int j = 0; j < 64; j++) {
        const float w = WoSh[cc][j];
        #pragma unroll
        for (int u = 0; u < 8; u++) acc[u] += w * MshT[j * 64 + i0 + u];
    }
    float* op = WT + (size_t)(b * Dsz + c0 + cc) * Dsz + h * DKsz + i0;
    *(float4*)op       = make_float4(acc[0], acc[1], acc[2], acc[3]);
    *(float4*)(op + 4) = make_float4(acc[4], acc[5], acc[6], acc[7]);
}

// ---------------------------------------------------------------------------
extern "C" void kernel_launch(void* const* d_in, const int* in_sizes, int n_in,
                              void* d_out, int out_size)
{
    const float* q  = (const float*)d_in[0];
    const float* k  = (const float*)d_in[1];
    const float* v  = (const float*)d_in[2];
    const float* wq = (const float*)d_in[3];
    const float* bq = (const float*)d_in[4];
    const float* wk = (const float*)d_in[5];
    const float* bk = (const float*)d_in[6];
    const float* wv = (const float*)d_in[7];
    const float* bv = (const float*)d_in[8];
    const float* wo = (const float*)d_in[9];
    const float* bo = (const float*)d_in[10];
    float* out = (float*)d_out;

    float *Q, *K, *V, *Mb, *WT;
    cudaGetSymbolAddress((void**)&Q,  g_Q);
    cudaGetSymbolAddress((void**)&K,  g_K);
    cudaGetSymbolAddress((void**)&V,  g_V);
    cudaGetSymbolAddress((void**)&Mb, g_M);
    cudaGetSymbolAddress((void**)&WT, g_WT);

    const dim3 gp(Dsz / 128, (Bsz * Ssz) / 128);   // (8, 32)
    sgemm_nt_bias<<<gp, 256>>>(q, wq, bq, Q, Bsz * Ssz, Dsz, Dsz);
    sgemm_nt_bias<<<gp, 256>>>(k, wk, bk, K, Bsz * Ssz, Dsz, Dsz);
    sgemm_nt_bias<<<gp, 256>>>(v, wv, bv, V, Bsz * Ssz, Dsz, Dsz);

    ktv_kernel<<<Bsz * Hsz, 256>>>(K, V, Mb);

    wcomb_kernel<<<dim3(Dsz / 32, Hsz, Bsz), 256>>>(Mb, wo, WT);

    for (int b = 0; b < Bsz; b++) {
        sgemm_nt_bias<<<dim3(Dsz / 128, Ssz / 128), 256>>>(
            Q  + (size_t)b * Ssz * Dsz,
            WT + (size_t)b * Dsz * Dsz,
            bo,
            out + (size_t)b * Ssz * Dsz,
            Ssz, Dsz, Dsz);
    }
}

// round 2
// speedup vs baseline: 2.6612x; 2.6612x over previous
#include <cuda_runtime.h>
#include <cuda_bf16.h>

// ---------------------------------------------------------------------------
// MultiHeadAttentionBlock — softmax is DISCARDED in the reference, so
// attention is LINEAR:  (Q K^T / 8) V == Q (K^T V / 8).  Pipeline:
//   1) Q,K,V projections: 3 GEMMs [4096x1024]x[1024x1024]^T   (tensor cores)
//   2) M[b,h] = K_h^T V_h / 8  (64x64 per head; split-S + reduce)
//   3) WcombT[b][c][h*64+i] = sum_j M[b,h][i,j] * Wo[c, h*64+j]
//   4) out_b = Q_b @ WcombT_b^T + bo  (batched GEMM, tensor cores)
// GEMMs use bf16 hi/lo split (3 MMAs) -> rel err ~1.5e-5.
// ---------------------------------------------------------------------------

#define Bsz 2
#define Ssz 2048
#define Dsz 1024
#define Hsz 16
#define DKsz 64
#define NCH 16   // S-chunks for ktv

// Scratch (no cudaMalloc allowed)
__device__ float g_Q[Bsz * Ssz * Dsz];
__device__ float g_K[Bsz * Ssz * Dsz];
__device__ float g_V[Bsz * Ssz * Dsz];
__device__ float g_Mpart[NCH * Bsz * Hsz * DKsz * DKsz];
__device__ float g_M[Bsz * Hsz * DKsz * DKsz];
__device__ float g_WT[Bsz * Dsz * Dsz];

// ---------------------------------------------------------------------------
// PTX helpers
// ---------------------------------------------------------------------------
__device__ __forceinline__ void ldsm4(unsigned r[4], const __nv_bfloat16* p) {
    unsigned a = (unsigned)__cvta_generic_to_shared(p);
    asm volatile("ldmatrix.sync.aligned.m8n8.x4.shared.b16 {%0,%1,%2,%3}, [%4];\n"
                 : "=r"(r[0]), "=r"(r[1]), "=r"(r[2]), "=r"(r[3]) : "r"(a));
}

__device__ __forceinline__ void mma_bf16(float c[4], const unsigned a[4], const unsigned b[2]) {
    asm volatile("mma.sync.aligned.m16n8k16.row.col.f32.bf16.bf16.f32 "
                 "{%0,%1,%2,%3}, {%4,%5,%6,%7}, {%8,%9}, {%0,%1,%2,%3};\n"
                 : "+f"(c[0]), "+f"(c[1]), "+f"(c[2]), "+f"(c[3])
                 : "r"(a[0]), "r"(a[1]), "r"(a[2]), "r"(a[3]), "r"(b[0]), "r"(b[1]));
}

__device__ __forceinline__ void split_store(__nv_bfloat16* hp, __nv_bfloat16* lp, float4 v) {
    __nv_bfloat16 h0 = __float2bfloat16_rn(v.x);
    __nv_bfloat16 h1 = __float2bfloat16_rn(v.y);
    __nv_bfloat16 h2 = __float2bfloat16_rn(v.z);
    __nv_bfloat16 h3 = __float2bfloat16_rn(v.w);
    __nv_bfloat16 l0 = __float2bfloat16_rn(v.x - __bfloat162float(h0));
    __nv_bfloat16 l1 = __float2bfloat16_rn(v.y - __bfloat162float(h1));
    __nv_bfloat16 l2 = __float2bfloat16_rn(v.z - __bfloat162float(h2));
    __nv_bfloat16 l3 = __float2bfloat16_rn(v.w - __bfloat162float(h3));
    reinterpret_cast<__nv_bfloat162*>(hp)[0] = __halves2bfloat162(h0, h1);
    reinterpret_cast<__nv_bfloat162*>(hp)[1] = __halves2bfloat162(h2, h3);
    reinterpret_cast<__nv_bfloat162*>(lp)[0] = __halves2bfloat162(l0, l1);
    reinterpret_cast<__nv_bfloat162*>(lp)[1] = __halves2bfloat162(l2, l3);
}

// ---------------------------------------------------------------------------
// Tensor-core GEMM (NT + bias, batched):
//   C[z][M,N] = A[z][M,K] @ B[z][N,K]^T + bias[N]
// 128x128 block tile, BK=32, 8 warps (2m x 4n), warp tile 64x32.
// bf16 hi/lo split: 3 MMAs per logical fp32 MMA.
// ---------------------------------------------------------------------------
__global__ __launch_bounds__(256)
void gemm_bf16split(const float* __restrict__ A, const float* __restrict__ B,
                    const float* __restrict__ bias, float* __restrict__ C,
                    int M, int N, int K, long sA, long sB, long sC)
{
    __shared__ __align__(16) __nv_bfloat16 Ah[128][40];
    __shared__ __align__(16) __nv_bfloat16 Al[128][40];
    __shared__ __align__(16) __nv_bfloat16 Bh[128][40];
    __shared__ __align__(16) __nv_bfloat16 Bl[128][40];

    A += (long)blockIdx.z * sA;
    B += (long)blockIdx.z * sB;
    C += (long)blockIdx.z * sC;
    const int bm = blockIdx.y * 128, bn = blockIdx.x * 128;
    const int tid = threadIdx.x, lane = tid & 31, warp = tid >> 5;
    const int wm = warp >> 2, wn = warp & 3;

    const int lrow = tid >> 3;        // 0..31
    const int lcol = (tid & 7) * 4;   // 0..28

    float4 rA[4], rB[4];
    #pragma unroll
    for (int i = 0; i < 4; i++) {
        rA[i] = *(const float4*)(A + (long)(bm + lrow + 32 * i) * K + lcol);
        rB[i] = *(const float4*)(B + (long)(bn + lrow + 32 * i) * K + lcol);
    }

    float acc[4][4][4];
    #pragma unroll
    for (int mt = 0; mt < 4; mt++)
        #pragma unroll
        for (int nt = 0; nt < 4; nt++)
            #pragma unroll
            for (int e = 0; e < 4; e++) acc[mt][nt][e] = 0.f;

    for (int k0 = 0; k0 < K; k0 += 32) {
        #pragma unroll
        for (int i = 0; i < 4; i++) {
            const int r = lrow + 32 * i;
            split_store(&Ah[r][lcol], &Al[r][lcol], rA[i]);
            split_store(&Bh[r][lcol], &Bl[r][lcol], rB[i]);
        }
        __syncthreads();

        if (k0 + 32 < K) {
            #pragma unroll
            for (int i = 0; i < 4; i++) {
                rA[i] = *(const float4*)(A + (long)(bm + lrow + 32 * i) * K + k0 + 32 + lcol);
                rB[i] = *(const float4*)(B + (long)(bn + lrow + 32 * i) * K + k0 + 32 + lcol);
            }
        }

        #pragma unroll
        for (int kk = 0; kk < 32; kk += 16) {
            unsigned aH[4][4], aL[4][4], bH[4][2], bL[4][2];
            const int arow = wm * 64 + (lane & 15);
            const int acol = kk + (lane >> 4) * 8;
            #pragma unroll
            for (int mt = 0; mt < 4; mt++) {
                ldsm4(aH[mt], &Ah[arow + mt * 16][acol]);
                ldsm4(aL[mt], &Al[arow + mt * 16][acol]);
            }
            const int g = lane >> 3;
            #pragma unroll
            for (int p = 0; p < 2; p++) {
                const int brow = wn * 32 + p * 16 + ((g >> 1) << 3) + (lane & 7);
                const int bcol = kk + (g & 1) * 8;
                unsigned t[4];
                ldsm4(t, &Bh[brow][bcol]);
                bH[2 * p][0] = t[0]; bH[2 * p][1] = t[1];
                bH[2 * p + 1][0] = t[2]; bH[2 * p + 1][1] = t[3];
                ldsm4(t, &Bl[brow][bcol]);
                bL[2 * p][0] = t[0]; bL[2 * p][1] = t[1];
                bL[2 * p + 1][0] = t[2]; bL[2 * p + 1][1] = t[3];
            }
            #pragma unroll
            for (int mt = 0; mt < 4; mt++)
                #pragma unroll
                for (int nt = 0; nt < 4; nt++) {
                    mma_bf16(acc[mt][nt], aH[mt], bH[nt]);
                    mma_bf16(acc[mt][nt], aH[mt], bL[nt]);
                    mma_bf16(acc[mt][nt], aL[mt], bH[nt]);
                }
        }
        __syncthreads();
    }

    // Epilogue: c layout m16n8 -> lane holds (row=l/4, cols=(l%4)*2,+1) and row+8
    const int crow = bm + wm * 64 + lane / 4;
    const int ccol0 = bn + wn * 32 + (lane % 4) * 2;
    #pragma unroll
    for (int mt = 0; mt < 4; mt++) {
        #pragma unroll
        for (int nt = 0; nt < 4; nt++) {
            const int col = ccol0 + nt * 8;
            const float2 bb = *(const float2*)(bias + col);
            const int row = crow + mt * 16;
            float2 o0, o1;
            o0.x = acc[mt][nt][0] + bb.x;
            o0.y = acc[mt][nt][1] + bb.y;
            o1.x = acc[mt][nt][2] + bb.x;
            o1.y = acc[mt][nt][3] + bb.y;
            *(float2*)(C + (long)row * N + col) = o0;
            *(float2*)(C + (long)(row + 8) * N + col) = o1;
        }
    }
}

// ---------------------------------------------------------------------------
// Partial M: g_Mpart[chunk][b,h][i][j] = sum_{s in chunk} K[b,s,h*64+i]*V[b,s,h*64+j]
// grid (Bsz*Hsz, NCH); chunk covers S/NCH = 128 rows.
// ---------------------------------------------------------------------------
__global__ __launch_bounds__(256)
void ktv_kernel(const float* __restrict__ Kp, const float* __restrict__ Vp,
                float* __restrict__ Mpart)
{
    __shared__ float Ks[32][64];
    __shared__ float Vs[32][64];
    const int bh = blockIdx.x;
    const int b = bh >> 4;
    const int h = bh & 15;
    const int chunk = blockIdx.y;
    const int tid = threadIdx.x;
    const int ti = (tid >> 4) * 4;
    const int tj = (tid & 15) * 4;
    const size_t base = (size_t)b * Ssz * Dsz + h * DKsz;

    float acc[4][4] = {};
    const int s_begin = chunk * (Ssz / NCH);
    for (int s0 = s_begin; s0 < s_begin + Ssz / NCH; s0 += 32) {
        #pragma unroll
        for (int it = 0; it < 2; it++) {
            const int idx = tid + it * 256;
            const int srow = idx >> 4;
            const int scol = (idx & 15) << 2;
            *(float4*)&Ks[srow][scol] =
                *(const float4*)(Kp + base + (size_t)(s0 + srow) * Dsz + scol);
            *(float4*)&Vs[srow][scol] =
                *(const float4*)(Vp + base + (size_t)(s0 + srow) * Dsz + scol);
        }
        __syncthreads();
        #pragma unroll
        for (int ss = 0; ss < 32; ss++) {
            float4 ka = *(const float4*)&Ks[ss][ti];
            float4 vb = *(const float4*)&Vs[ss][tj];
            const float a[4] = {ka.x, ka.y, ka.z, ka.w};
            const float w[4] = {vb.x, vb.y, vb.z, vb.w};
            #pragma unroll
            for (int i = 0; i < 4; i++)
                #pragma unroll
                for (int j = 0; j < 4; j++) acc[i][j] += a[i] * w[j];
        }
        __syncthreads();
    }
    float* outp = Mpart + (long)chunk * (Bsz * Hsz * DKsz * DKsz) + (long)bh * (DKsz * DKsz);
    #pragma unroll
    for (int i = 0; i < 4; i++)
        *(float4*)(outp + (ti + i) * DKsz + tj) = make_float4(acc[i][0], acc[i][1], acc[i][2], acc[i][3]);
}

// Deterministic reduction of the NCH partials, with 1/8 scale.
__global__ __launch_bounds__(256)
void ktv_reduce(const float* __restrict__ Mpart, float* __restrict__ Mout)
{
    const int idx = blockIdx.x * 256 + threadIdx.x;   // 0 .. 131071
    float s = 0.f;
    #pragma unroll
    for (int c = 0; c < NCH; c++)
        s += Mpart[(long)c * (Bsz * Hsz * DKsz * DKsz) + idx];
    Mout[idx] = s * 0.125f;
}

// ---------------------------------------------------------------------------
// WcombT[b][c][h*64+i] = sum_j M[b,h][i][j] * Wo[c][h*64+j]
// ---------------------------------------------------------------------------
__global__ __launch_bounds__(256)
void wcomb_kernel(const float* __restrict__ Mh, const float* __restrict__ Wo,
                  float* __restrict__ WT)
{
    __shared__ float MshT[64 * 64];   // [j][i]
    __shared__ float WoSh[32][64];
    const int c0 = blockIdx.x * 32;
    const int h  = blockIdx.y;
    const int b  = blockIdx.z;
    const int tid = threadIdx.x;

    const float* Mp = Mh + (size_t)(b * Hsz + h) * (DKsz * DKsz);
    #pragma unroll
    for (int t = tid; t < 4096; t += 256) {
        const int i = t >> 6, j = t & 63;
        MshT[j * 64 + i] = Mp[t];
    }
    #pragma unroll
    for (int t = tid; t < 2048; t += 256) {
        const int cc = t >> 6, j = t & 63;
        WoSh[cc][j] = Wo[(size_t)(c0 + cc) * Dsz + h * DKsz + j];
    }
    __syncthreads();

    const int cc = tid >> 3;
    const int i0 = (tid & 7) * 8;
    float acc[8] = {};
    #pragma unroll
    for (int j = 0; j < 64; j++) {
        const float w = WoSh[cc][j];
        #pragma unroll
        for (int u = 0; u < 8; u++) acc[u] += w * MshT[j * 64 + i0 + u];
    }
    float* op = WT + (size_t)(b * Dsz + c0 + cc) * Dsz + h * DKsz + i0;
    *(float4*)op       = make_float4(acc[0], acc[1], acc[2], acc[3]);
    *(float4*)(op + 4) = make_float4(acc[4], acc[5], acc[6], acc[7]);
}

// ---------------------------------------------------------------------------
extern "C" void kernel_launch(void* const* d_in, const int* in_sizes, int n_in,
                              void* d_out, int out_size)
{
    const float* q  = (const float*)d_in[0];
    const float* k  = (const float*)d_in[1];
    const float* v  = (const float*)d_in[2];
    const float* wq = (const float*)d_in[3];
    const float* bq = (const float*)d_in[4];
    const float* wk = (const float*)d_in[5];
    const float* bk = (const float*)d_in[6];
    const float* wv = (const float*)d_in[7];
    const float* bv = (const float*)d_in[8];
    const float* wo = (const float*)d_in[9];
    const float* bo = (const float*)d_in[10];
    float* out = (float*)d_out;

    float *Q, *K, *V, *Mp, *Mb, *WT;
    cudaGetSymbolAddress((void**)&Q,  g_Q);
    cudaGetSymbolAddress((void**)&K,  g_K);
    cudaGetSymbolAddress((void**)&V,  g_V);
    cudaGetSymbolAddress((void**)&Mp, g_Mpart);
    cudaGetSymbolAddress((void**)&Mb, g_M);
    cudaGetSymbolAddress((void**)&WT, g_WT);

    // 1) Projections (tensor cores, bf16-split)
    const dim3 gp(Dsz / 128, (Bsz * Ssz) / 128, 1);   // (8, 32, 1)
    gemm_bf16split<<<gp, 256>>>(q, wq, bq, Q, Bsz * Ssz, Dsz, Dsz, 0, 0, 0);
    gemm_bf16split<<<gp, 256>>>(k, wk, bk, K, Bsz * Ssz, Dsz, Dsz, 0, 0, 0);
    gemm_bf16split<<<gp, 256>>>(v, wv, bv, V, Bsz * Ssz, Dsz, Dsz, 0, 0, 0);

    // 2) M = K^T V / 8 (split-S partials + deterministic reduce)
    ktv_kernel<<<dim3(Bsz * Hsz, NCH), 256>>>(K, V, Mp);
    ktv_reduce<<<(Bsz * Hsz * DKsz * DKsz) / 256, 256>>>(Mp, Mb);

    // 3) Fold attention into output weight
    wcomb_kernel<<<dim3(Dsz / 32, Hsz, Bsz), 256>>>(Mb, wo, WT);

    // 4) Output GEMM (batched over B)
    gemm_bf16split<<<dim3(Dsz / 128, Ssz / 128, Bsz), 256>>>(
        Q, WT, bo, out, Ssz, Dsz, Dsz,
        (long)Ssz * Dsz, (long)Dsz * Dsz, (long)Ssz * Dsz);
}